// round 8
// baseline (speedup 1.0000x reference)
#include <cuda_runtime.h>
#include <cstdint>

#define THREADS 256

// ---------------- helpers ----------------
__device__ __forceinline__ uint32_t f2tf32(float f){
    uint32_t u; asm("cvt.rna.tf32.f32 %0, %1;" : "=r"(u) : "f"(f)); return u;
}
__device__ __forceinline__ uint32_t smem_u32(const void* p){
    uint32_t a;
    asm("{ .reg .u64 t; cvta.to.shared.u64 t, %1; cvt.u32.u64 %0, t; }" : "=r"(a) : "l"(p));
    return a;
}
__device__ __forceinline__ void mma1688(float d[4], const uint32_t a[4], const uint32_t b0, const uint32_t b1){
    asm volatile("mma.sync.aligned.m16n8k8.row.col.f32.tf32.tf32.f32 "
        "{%0,%1,%2,%3}, {%4,%5,%6,%7}, {%8,%9}, {%0,%1,%2,%3};"
        : "+f"(d[0]), "+f"(d[1]), "+f"(d[2]), "+f"(d[3])
        : "r"(a[0]), "r"(a[1]), "r"(a[2]), "r"(a[3]), "r"(b0), "r"(b1));
}
#define CPA16(d, s)  asm volatile("cp.async.cg.shared.global [%0], [%1], 16;" :: "r"(d), "l"(s))
#define CPA_COMMIT() asm volatile("cp.async.commit_group;" ::: "memory")
#define CPA_WAIT0()  asm volatile("cp.async.wait_group 0;" ::: "memory")

// ---------------- merged weights, fragment-ordered, tf32-rounded ----------------
// gW01f (stage-1 B operand), 16 chunks x 4096, B-fragment order:
//   fi = ((kk*8 + nt)*32 + lane)*2 + reg ; k=m = kk*8+(lane&3)+4*reg, n=oo = nt*8+(lane>>2)
// gW23f (stage-2 A operand), 16 chunks x 4096, A-fragment order:
//   fi = ((mt*8 + kk)*32 + lane)*4 + r ; o23 = mt*16+(lane>>2)+8*(r&1), k=q = kk*8+(lane&3)+4*(r>>1)
__device__ __align__(16) float gW01f[65536];
__device__ __align__(16) float gW23f[65536];

__global__ void tt_pre(const float* __restrict__ w0, const float* __restrict__ w1,
                       const float* __restrict__ w2, const float* __restrict__ w3) {
    int tid = blockIdx.x * blockDim.x + threadIdx.x;
    if (tid < 65536) {
        int c    = tid >> 12;
        int fi   = tid & 4095;
        int reg  = fi & 1;
        int lane = (fi >> 1) & 31;
        int nt   = (fi >> 6) & 7;
        int kk   = fi >> 9;
        int m  = kk*8 + (lane & 3) + 4*reg;
        int oo = nt*8 + (lane >> 2);
        int o0 = oo >> 3, o1 = oo & 7;
        int i0 = m >> 3,  i1 = m & 7;
        float s = 0.f;
        #pragma unroll
        for (int r1 = 0; r1 < 16; r1++)
            s += w0[(o0*16 + r1)*8 + i0] * w1[(o1*16 + c)*128 + r1*8 + i1];
        gW01f[c*4096 + fi] = __uint_as_float(f2tf32(s));
    } else if (tid < 131072) {
        int t    = tid - 65536;
        int c    = t >> 12;
        int fi   = t & 4095;
        int r    = fi & 3;
        int lane = (fi >> 2) & 31;
        int kk   = (fi >> 7) & 7;
        int mt   = fi >> 10;
        int o23 = mt*16 + (lane >> 2) + 8*(r & 1);
        int q   = kk*8 + (lane & 3) + 4*(r >> 1);
        int o2 = o23 >> 3, o3 = o23 & 7;
        int i2 = q >> 3,   i3 = q & 7;
        float s = 0.f;
        #pragma unroll
        for (int r3 = 0; r3 < 16; r3++)
            s += w2[(o2*16 + r3)*128 + c*8 + i2] * w3[o3*128 + r3*8 + i3];
        gW23f[c*4096 + fi] = __uint_as_float(f2tf32(s));
    }
}

// ---------------- SMEM map (float indices), 96 KB total -> 2 CTAs/SM ----------------
// A1F [0, 8192)       : X fragments (rows (b,q), k=m), 8 tiles x 8 kk x 32 x 4
// B1F [8192, +2*4096) : W01 chunk double-buffer
// B2F [16384, +2*4096): W23 chunk double-buffer
#define B1_OFF 8192
#define B2_OFF 16384
#define SMF_TOTAL 24576

__global__ __launch_bounds__(THREADS, 2)
void tt_mma(const float* __restrict__ x, const float* __restrict__ bias,
            float* __restrict__ out) {
    extern __shared__ float smf[];
    float* A1F = smf;
    float* B1F = smf + B1_OFF;
    float* B2F = smf + B2_OFF;

    const int tid  = threadIdx.x;
    const int wid  = tid >> 5;
    const int lane = tid & 31;
    const uint32_t sb  = smem_u32(smf);
    const uint32_t B1a = sb + B1_OFF*4u;
    const uint32_t B2a = sb + B2_OFF*4u;

    // prefetch weight chunk 0 (16KB each = 1024 float4)
    {
        const float4* s01 = (const float4*)gW01f;
        const float4* s23 = (const float4*)gW23f;
        #pragma unroll
        for (int i = 0; i < 4; i++) CPA16(B1a + (tid + i*256)*16, s01 + tid + i*256);
        #pragma unroll
        for (int i = 0; i < 4; i++) CPA16(B2a + (tid + i*256)*16, s23 + tid + i*256);
        CPA_COMMIT();
    }

    // ---- stage X (2 batch rows) into A1 fragment layout (tf32-rounded) ----
    const long long b0 = (long long)blockIdx.x * 2;
    {
        const float4* xp = (const float4*)(x + b0 * 4096);
        #pragma unroll 4
        for (int e = tid; e < 2048; e += THREADS) {
            float4 v = xp[e];
            int idx = e * 4;
            int b = idx >> 12, m = (idx >> 6) & 63, q = idx & 63;  // q % 4 == 0
            int kk = m >> 3;
            int rhi = ((m & 7) >> 2);
            int ld  = (m & 3);
            float vv[4] = {v.x, v.y, v.z, v.w};
            #pragma unroll
            for (int j = 0; j < 4; j++) {
                int row = b*64 + q + j;
                int tile = row >> 4, r = row & 15;
                int ln = (r & 7)*4 + ld;
                int rg = (r >> 3) + 2*rhi;
                A1F[((tile*8 + kk)*32 + ln)*4 + rg] = __uint_as_float(f2tf32(vv[j]));
            }
        }
    }

    // warp -> (batch bw, oo-quarter ooq): warp owns FULL q (all stage-2 k), 16 oo cols
    const int bw  = wid >> 2;
    const int ooq = wid & 3;

    float acc[4][2][4];   // [o23-tile][ntl][frag] = 32 regs
    #pragma unroll
    for (int mt = 0; mt < 4; mt++)
        #pragma unroll
        for (int ntl = 0; ntl < 2; ntl++)
            #pragma unroll
            for (int r = 0; r < 4; r++) acc[mt][ntl][r] = 0.f;

    // shuffle source lanes for d -> B-fragment conversion
    const int src0 = 4*(lane & 3) + ((lane >> 2) >> 1);
    const int src1 = src0 + 16;
    const int colpar = (lane >> 2) & 1;

    for (int c = 0; c < 16; c++) {
        const int cb = c & 1;
        CPA_WAIT0();
        __syncthreads();   // weights visible; WAR on weight buffers cleared

        if (c < 15) {
            const int nb = cb ^ 1;
            const float4* s01 = (const float4*)(gW01f + (c + 1)*4096);
            const float4* s23 = (const float4*)(gW23f + (c + 1)*4096);
            #pragma unroll
            for (int i = 0; i < 4; i++) CPA16(B1a + nb*16384 + (tid + i*256)*16, s01 + tid + i*256);
            #pragma unroll
            for (int i = 0; i < 4; i++) CPA16(B2a + nb*16384 + (tid + i*256)*16, s23 + tid + i*256);
            CPA_COMMIT();
        }

        const float* B1 = B1F + cb*4096;
        const float* B2 = B2F + cb*4096;

        // ---- stage 1: d[64 q x 16 oo] = X_b @ W01_c (warp's oo slice) ----
        float d[4][2][4];
        #pragma unroll
        for (int t = 0; t < 4; t++)
            #pragma unroll
            for (int ntl = 0; ntl < 2; ntl++)
                #pragma unroll
                for (int r = 0; r < 4; r++) d[t][ntl][r] = 0.f;

        #pragma unroll
        for (int kk = 0; kk < 8; kk++) {
            uint32_t bfr[2][2];
            #pragma unroll
            for (int ntl = 0; ntl < 2; ntl++) {
                float2 bf = *(const float2*)(B1 + ((kk*8 + ooq*2 + ntl)*32 + lane)*2);
                bfr[ntl][0] = __float_as_uint(bf.x);
                bfr[ntl][1] = __float_as_uint(bf.y);
            }
            #pragma unroll
            for (int t = 0; t < 4; t++) {
                float4 af = *(const float4*)(A1F + (((bw*4 + t)*8 + kk)*32 + lane)*4);
                uint32_t a[4] = {__float_as_uint(af.x), __float_as_uint(af.y),
                                 __float_as_uint(af.z), __float_as_uint(af.w)};
                #pragma unroll
                for (int ntl = 0; ntl < 2; ntl++)
                    mma1688(d[t][ntl], a, bfr[ntl][0], bfr[ntl][1]);
            }
        }

        // round t1 to tf32 in registers
        #pragma unroll
        for (int t = 0; t < 4; t++)
            #pragma unroll
            for (int ntl = 0; ntl < 2; ntl++)
                #pragma unroll
                for (int r = 0; r < 4; r++)
                    d[t][ntl][r] = __uint_as_float(f2tf32(d[t][ntl][r]));

        // ---- stage 2: ACC[o23 x oo-slice] += W23_c(A-frag) @ d(B-frag via shuffles) ----
        #pragma unroll
        for (int kkg = 0; kkg < 8; kkg++) {
            const int t = kkg >> 1, kkp = kkg & 1;
            uint32_t bs[2][2];
            #pragma unroll
            for (int ntl = 0; ntl < 2; ntl++) {
                float v00 = __shfl_sync(0xffffffffu, d[t][ntl][2*kkp + 0], src0);
                float v01 = __shfl_sync(0xffffffffu, d[t][ntl][2*kkp + 1], src0);
                float v10 = __shfl_sync(0xffffffffu, d[t][ntl][2*kkp + 0], src1);
                float v11 = __shfl_sync(0xffffffffu, d[t][ntl][2*kkp + 1], src1);
                bs[ntl][0] = __float_as_uint(colpar ? v01 : v00);
                bs[ntl][1] = __float_as_uint(colpar ? v11 : v10);
            }
            #pragma unroll
            for (int mt = 0; mt < 4; mt++) {
                float4 af = *(const float4*)(B2 + ((mt*8 + kkg)*32 + lane)*4);
                uint32_t a[4] = {__float_as_uint(af.x), __float_as_uint(af.y),
                                 __float_as_uint(af.z), __float_as_uint(af.w)};
                #pragma unroll
                for (int ntl = 0; ntl < 2; ntl++)
                    mma1688(acc[mt][ntl], a, bs[ntl][0], bs[ntl][1]);
            }
        }
    }

    // ---- epilogue: no reduction needed (warp owns full k) ----
    {
        const int g = lane >> 2, tq = lane & 3;
        float* ob = out + (b0 + bw) * 4096;
        #pragma unroll
        for (int mt = 0; mt < 4; mt++)
            #pragma unroll
            for (int ntl = 0; ntl < 2; ntl++)
                #pragma unroll
                for (int r = 0; r < 4; r++) {
                    int o23 = mt*16 + g + 8*(r >> 1);
                    int oo  = (ooq*2 + ntl)*8 + 2*tq + (r & 1);
                    int col = oo*64 + o23;
                    ob[col] = acc[mt][ntl][r] + __ldg(bias + col);
                }
    }
}

extern "C" void kernel_launch(void* const* d_in, const int* in_sizes, int n_in,
                              void* d_out, int out_size) {
    const float* x    = (const float*)d_in[0];
    const float* w0   = (const float*)d_in[1];
    const float* w1   = (const float*)d_in[2];
    const float* w2   = (const float*)d_in[3];
    const float* w3   = (const float*)d_in[4];
    const float* bias = (const float*)d_in[5];
    float* out = (float*)d_out;

    tt_pre<<<512, 256>>>(w0, w1, w2, w3);

    cudaFuncSetAttribute(tt_mma, cudaFuncAttributeMaxDynamicSharedMemorySize,
                         SMF_TOTAL * (int)sizeof(float));
    tt_mma<<<16384 / 2, THREADS, SMF_TOTAL * (int)sizeof(float)>>>(x, bias, out);
}

// round 10
// speedup vs baseline: 1.6057x; 1.6057x over previous
#include <cuda_runtime.h>
#include <cuda_fp16.h>
#include <cstdint>

#define THREADS 256

// ---------------- helpers ----------------
__device__ __forceinline__ uint32_t smem_u32(const void* p){
    uint32_t a;
    asm("{ .reg .u64 t; cvta.to.shared.u64 t, %1; cvt.u32.u64 %0, t; }" : "=r"(a) : "l"(p));
    return a;
}
__device__ __forceinline__ uint32_t packh2(float lo, float hi){
    __half2 h = __floats2half2_rn(lo, hi);
    return *reinterpret_cast<uint32_t*>(&h);
}
__device__ __forceinline__ void mma16816(float d[4], const uint32_t a[4],
                                         const uint32_t b0, const uint32_t b1){
    asm volatile("mma.sync.aligned.m16n8k16.row.col.f32.f16.f16.f32 "
        "{%0,%1,%2,%3}, {%4,%5,%6,%7}, {%8,%9}, {%0,%1,%2,%3};"
        : "+f"(d[0]), "+f"(d[1]), "+f"(d[2]), "+f"(d[3])
        : "r"(a[0]), "r"(a[1]), "r"(a[2]), "r"(a[3]), "r"(b0), "r"(b1));
}
#define CPA16(d, s)  asm volatile("cp.async.cg.shared.global [%0], [%1], 16;" :: "r"(d), "l"(s))
#define CPA_COMMIT() asm volatile("cp.async.commit_group;" ::: "memory")
#define CPA_WAIT0()  asm volatile("cp.async.wait_group 0;" ::: "memory")

// ---------------- merged weights, fp16 fragment-ordered (half2 = uint32) ----------------
// gW01h (stage-1 B operand), 16 chunks x 2048 u32, m16n8k16 B-frag order:
//   idx = ((kk*8 + nt)*32 + lane)*2 + rb ; half2 lo/hi = k = kk*16 + 2*(lane&3) + 8*rb + {0,1}
//   k = m (i0,i1); n = oo = nt*8 + (lane>>2)
// gW23h (stage-2 A operand), 16 chunks x 2048 u32, m16n8k16 A-frag order:
//   idx = ((mt*4 + kk)*32 + lane)*4 + ra ; o23 = mt*16 + (lane>>2) + 8*(ra&1)
//   half2 lo/hi = k = q = kk*16 + 2*(lane&3) + 8*(ra>>1) + {0,1}
__device__ __align__(16) uint32_t gW01h[32768];
__device__ __align__(16) uint32_t gW23h[32768];

__global__ void tt_pre(const float* __restrict__ w0, const float* __restrict__ w1,
                       const float* __restrict__ w2, const float* __restrict__ w3) {
    int tid = blockIdx.x * blockDim.x + threadIdx.x;
    if (tid < 32768) {
        int c    = tid >> 11;
        int rem  = tid & 2047;
        int rb   = rem & 1;
        int lane = (rem >> 1) & 31;
        int nt   = (rem >> 6) & 7;
        int kk   = rem >> 9;                 // [0,4)
        int kb   = kk*16 + 2*(lane & 3) + 8*rb;
        int oo   = nt*8 + (lane >> 2);
        int o0 = oo >> 3, o1 = oo & 7;
        float s[2];
        #pragma unroll
        for (int h = 0; h < 2; h++) {
            int m = kb + h;
            int i0 = m >> 3, i1 = m & 7;
            float v = 0.f;
            #pragma unroll
            for (int r1 = 0; r1 < 16; r1++)
                v += w0[(o0*16 + r1)*8 + i0] * w1[(o1*16 + c)*128 + r1*8 + i1];
            s[h] = v;
        }
        gW01h[c*2048 + rem] = packh2(s[0], s[1]);
    } else if (tid < 65536) {
        int t    = tid - 32768;
        int c    = t >> 11;
        int rem  = t & 2047;
        int ra   = rem & 3;
        int lane = (rem >> 2) & 31;
        int kk   = (rem >> 7) & 3;
        int mt   = rem >> 9;                 // [0,4)
        int o23  = mt*16 + (lane >> 2) + 8*(ra & 1);
        int qb   = kk*16 + 2*(lane & 3) + 8*(ra >> 1);
        int o2 = o23 >> 3, o3 = o23 & 7;
        float s[2];
        #pragma unroll
        for (int h = 0; h < 2; h++) {
            int q = qb + h;
            int i2 = q >> 3, i3 = q & 7;
            float v = 0.f;
            #pragma unroll
            for (int r3 = 0; r3 < 16; r3++)
                v += w2[(o2*16 + r3)*128 + c*8 + i2] * w3[o3*128 + r3*8 + i3];
            s[h] = v;
        }
        gW23h[c*2048 + rem] = packh2(s[0], s[1]);
    }
}

// ---------------- SMEM map (uint32 indices), 48 KB -> 2 CTAs/SM ----------------
// A1H [0, 4096)      : X A-fragments fp16, 8 tiles x 4 kk x 32 lanes x 4 regs
// B1H [4096, +2*2048): W01 chunk double-buffer
// B2H [8192, +2*2048): W23 chunk double-buffer
#define B1_OFF 4096
#define B2_OFF 8192
#define SMU_TOTAL 12288

__global__ __launch_bounds__(THREADS, 2)
void tt_mma(const float* __restrict__ x, const float* __restrict__ bias,
            float* __restrict__ out) {
    extern __shared__ uint32_t smu[];
    uint32_t* A1H = smu;
    uint32_t* B1H = smu + B1_OFF;
    uint32_t* B2H = smu + B2_OFF;

    const int tid  = threadIdx.x;
    const int wid  = tid >> 5;
    const int lane = tid & 31;
    const uint32_t sb  = smem_u32(smu);
    const uint32_t B1a = sb + B1_OFF*4u;
    const uint32_t B2a = sb + B2_OFF*4u;

    // prefetch weight chunk 0 (8KB each = 512 uint4)
    {
        const uint4* s01 = (const uint4*)gW01h;
        const uint4* s23 = (const uint4*)gW23h;
        #pragma unroll
        for (int i = 0; i < 2; i++) CPA16(B1a + (tid + i*256)*16, s01 + tid + i*256);
        #pragma unroll
        for (int i = 0; i < 2; i++) CPA16(B2a + (tid + i*256)*16, s23 + tid + i*256);
        CPA_COMMIT();
    }

    // ---- stage X (2 batch rows) into A1 fp16 A-fragment layout ----
    // FIX vs round 9: half2 must pack (m, m+1) at the SAME row. Each thread
    // loads two float4s one m-row apart (4 consecutive q at m=2u and m=2u+1),
    // producing 4 correct half2 values.
    const long long b0 = (long long)blockIdx.x * 2;
    {
        const float4* xp = (const float4*)(x + b0 * 4096);
        #pragma unroll 4
        for (int e = tid; e < 1024; e += THREADS) {
            int b    = e >> 9;            // batch row (0..1)
            int rest = e & 511;
            int u    = rest >> 4;         // half2 unit along k: m pair = (2u, 2u+1), u in [0,32)
            int qq   = rest & 15;         // q quad
            float4 va = xp[b*1024 + (2*u)*16 + qq];       // m = 2u,   q = 4qq..4qq+3
            float4 vb = xp[b*1024 + (2*u + 1)*16 + qq];   // m = 2u+1, q = 4qq..4qq+3
            int kk  = u >> 3;
            int l3  = u & 3;
            int rhi = 2*((u >> 2) & 1);
            float av[4] = {va.x, va.y, va.z, va.w};
            float bv[4] = {vb.x, vb.y, vb.z, vb.w};
            #pragma unroll
            for (int j = 0; j < 4; j++) {
                int row  = b*64 + qq*4 + j;
                int tg   = row >> 4;
                int rowr = row & 15;
                int ln   = (rowr & 7)*4 + l3;
                int ra   = (rowr >> 3) + rhi;
                A1H[((tg*4 + kk)*32 + ln)*4 + ra] = packh2(av[j], bv[j]);
            }
        }
    }

    // warp -> (batch bw, oo-quarter ooq): warp owns FULL q, 16 oo cols
    const int bw  = wid >> 2;
    const int ooq = wid & 3;

    float acc[4][2][4];   // [o23-tile][ntl][frag]
    #pragma unroll
    for (int mt = 0; mt < 4; mt++)
        #pragma unroll
        for (int ntl = 0; ntl < 2; ntl++)
            #pragma unroll
            for (int r = 0; r < 4; r++) acc[mt][ntl][r] = 0.f;

    // shuffle source lanes for d(C-frag) -> stage-2 B-frag(fp16) conversion
    const int sA = 8*(lane & 3) + ((lane >> 2) >> 1);
    const int sB = sA + 4;
    const int colpar = (lane >> 2) & 1;

    for (int c = 0; c < 16; c++) {
        const int cb = c & 1;
        CPA_WAIT0();
        __syncthreads();   // weights visible; WAR on weight buffers cleared

        if (c < 15) {
            const int nb = cb ^ 1;
            const uint4* s01 = (const uint4*)(gW01h + (c + 1)*2048);
            const uint4* s23 = (const uint4*)(gW23h + (c + 1)*2048);
            #pragma unroll
            for (int i = 0; i < 2; i++) CPA16(B1a + nb*8192 + (tid + i*256)*16, s01 + tid + i*256);
            #pragma unroll
            for (int i = 0; i < 2; i++) CPA16(B2a + nb*8192 + (tid + i*256)*16, s23 + tid + i*256);
            CPA_COMMIT();
        }

        const uint32_t* B1 = B1H + cb*2048;
        const uint32_t* B2 = B2H + cb*2048;

        // ---- stage 1: d[64 q x 16 oo] = X_b @ W01_c (4 ksteps of 16) ----
        float d[4][2][4];
        #pragma unroll
        for (int t = 0; t < 4; t++)
            #pragma unroll
            for (int ntl = 0; ntl < 2; ntl++)
                #pragma unroll
                for (int r = 0; r < 4; r++) d[t][ntl][r] = 0.f;

        #pragma unroll
        for (int kk = 0; kk < 4; kk++) {
            uint32_t bfr[2][2];
            #pragma unroll
            for (int ntl = 0; ntl < 2; ntl++) {
                uint2 bf = *(const uint2*)(B1 + ((kk*8 + ooq*2 + ntl)*32 + lane)*2);
                bfr[ntl][0] = bf.x; bfr[ntl][1] = bf.y;
            }
            #pragma unroll
            for (int t = 0; t < 4; t++) {
                uint4 af = *(const uint4*)(A1H + (((bw*4 + t)*4 + kk)*32 + lane)*4);
                uint32_t a[4] = {af.x, af.y, af.z, af.w};
                #pragma unroll
                for (int ntl = 0; ntl < 2; ntl++)
                    mma16816(d[t][ntl], a, bfr[ntl][0], bfr[ntl][1]);
            }
        }

        // ---- stage 2: ACC[o23 x oo-slice] += W23_c(A-frag) @ d(B-frag via shuffles) ----
        #pragma unroll
        for (int K = 0; K < 4; K++) {       // kstep over q (d tile t = K)
            uint32_t bs[2][2];
            #pragma unroll
            for (int ntl = 0; ntl < 2; ntl++)
                #pragma unroll
                for (int rb = 0; rb < 2; rb++) {
                    float v0a = __shfl_sync(0xffffffffu, d[K][ntl][2*rb + 0], sA);
                    float v0b = __shfl_sync(0xffffffffu, d[K][ntl][2*rb + 1], sA);
                    float v1a = __shfl_sync(0xffffffffu, d[K][ntl][2*rb + 0], sB);
                    float v1b = __shfl_sync(0xffffffffu, d[K][ntl][2*rb + 1], sB);
                    float lo = colpar ? v0b : v0a;
                    float hi = colpar ? v1b : v1a;
                    bs[ntl][rb] = packh2(lo, hi);
                }
            #pragma unroll
            for (int mt = 0; mt < 4; mt++) {
                uint4 af = *(const uint4*)(B2 + ((mt*4 + K)*32 + lane)*4);
                uint32_t a[4] = {af.x, af.y, af.z, af.w};
                #pragma unroll
                for (int ntl = 0; ntl < 2; ntl++)
                    mma16816(acc[mt][ntl], a, bs[ntl][0], bs[ntl][1]);
            }
        }
    }

    // ---- epilogue: acc element (row=o23, col=oo) + bias -> out ----
    {
        const int g = lane >> 2, tq = lane & 3;
        float* ob = out + (b0 + bw) * 4096;
        #pragma unroll
        for (int mt = 0; mt < 4; mt++)
            #pragma unroll
            for (int ntl = 0; ntl < 2; ntl++)
                #pragma unroll
                for (int r = 0; r < 4; r++) {
                    int o23 = mt*16 + g + 8*(r >> 1);
                    int oo  = (ooq*2 + ntl)*8 + 2*tq + (r & 1);
                    int col = oo*64 + o23;
                    ob[col] = acc[mt][ntl][r] + __ldg(bias + col);
                }
    }
}

extern "C" void kernel_launch(void* const* d_in, const int* in_sizes, int n_in,
                              void* d_out, int out_size) {
    const float* x    = (const float*)d_in[0];
    const float* w0   = (const float*)d_in[1];
    const float* w1   = (const float*)d_in[2];
    const float* w2   = (const float*)d_in[3];
    const float* w3   = (const float*)d_in[4];
    const float* bias = (const float*)d_in[5];
    float* out = (float*)d_out;

    tt_pre<<<256, 256>>>(w0, w1, w2, w3);

    cudaFuncSetAttribute(tt_mma, cudaFuncAttributeMaxDynamicSharedMemorySize,
                         SMU_TOTAL * (int)sizeof(uint32_t));
    tt_mma<<<16384 / 2, THREADS, SMU_TOTAL * (int)sizeof(uint32_t)>>>(x, bias, out);
}

// round 11
// speedup vs baseline: 2.0219x; 1.2592x over previous
#include <cuda_runtime.h>
#include <cuda_fp16.h>
#include <cstdint>

#define THREADS 256

// ---------------- helpers ----------------
__device__ __forceinline__ uint32_t smem_u32(const void* p){
    uint32_t a;
    asm("{ .reg .u64 t; cvta.to.shared.u64 t, %1; cvt.u32.u64 %0, t; }" : "=r"(a) : "l"(p));
    return a;
}
__device__ __forceinline__ uint32_t packh2(float lo, float hi){
    __half2 h = __floats2half2_rn(lo, hi);
    return *reinterpret_cast<uint32_t*>(&h);
}
__device__ __forceinline__ void mma16816(float d[4], const uint32_t a[4],
                                         const uint32_t b0, const uint32_t b1){
    asm volatile("mma.sync.aligned.m16n8k16.row.col.f32.f16.f16.f32 "
        "{%0,%1,%2,%3}, {%4,%5,%6,%7}, {%8,%9}, {%0,%1,%2,%3};"
        : "+f"(d[0]), "+f"(d[1]), "+f"(d[2]), "+f"(d[3])
        : "r"(a[0]), "r"(a[1]), "r"(a[2]), "r"(a[3]), "r"(b0), "r"(b1));
}
#define CPA16(d, s)  asm volatile("cp.async.cg.shared.global [%0], [%1], 16;" :: "r"(d), "l"(s))
#define CPA_COMMIT() asm volatile("cp.async.commit_group;" ::: "memory")
#define CPA_WAIT0()  asm volatile("cp.async.wait_group 0;" ::: "memory")

// ---------------- merged weights, fp16 fragment-ordered (half2 = uint32) ----------------
// gW01h (stage-1 A operand, M=oo), 16 chunks x 2048 u32, m16n8k16 A-frag order:
//   idx = ((ooq*4 + kk)*32 + lane)*4 + ra
//   oo = ooq*16 + (lane>>2) + 8*(ra&1); half2 = m = kk*16 + 2*(lane&3) + 8*(ra>>1) + {0,1}
// gW23h (stage-2 A operand, M=o23), 16 chunks x 2048 u32, m16n8k16 A-frag order:
//   idx = ((mt*4 + kk)*32 + lane)*4 + ra
//   o23 = mt*16 + (lane>>2) + 8*(ra&1); half2 = q = kk*16 + 2*(lane&3) + 8*(ra>>1) + {0,1}
__device__ __align__(16) uint32_t gW01h[32768];
__device__ __align__(16) uint32_t gW23h[32768];

__global__ void tt_pre(const float* __restrict__ w0, const float* __restrict__ w1,
                       const float* __restrict__ w2, const float* __restrict__ w3) {
    int tid = blockIdx.x * blockDim.x + threadIdx.x;
    if (tid < 32768) {
        int c    = tid >> 11;
        int rem  = tid & 2047;
        int ra   = rem & 3;
        int lane = (rem >> 2) & 31;
        int kk   = (rem >> 7) & 3;
        int ooq  = rem >> 9;                 // [0,4)
        int oo   = ooq*16 + (lane >> 2) + 8*(ra & 1);
        int mb   = kk*16 + 2*(lane & 3) + 8*(ra >> 1);
        int o0 = oo >> 3, o1 = oo & 7;
        float s[2];
        #pragma unroll
        for (int h = 0; h < 2; h++) {
            int m = mb + h;
            int i0 = m >> 3, i1 = m & 7;
            float v = 0.f;
            #pragma unroll
            for (int r1 = 0; r1 < 16; r1++)
                v += w0[(o0*16 + r1)*8 + i0] * w1[(o1*16 + c)*128 + r1*8 + i1];
            s[h] = v;
        }
        gW01h[c*2048 + rem] = packh2(s[0], s[1]);
    } else if (tid < 65536) {
        int t    = tid - 32768;
        int c    = t >> 11;
        int rem  = t & 2047;
        int ra   = rem & 3;
        int lane = (rem >> 2) & 31;
        int kk   = (rem >> 7) & 3;
        int mt   = rem >> 9;                 // [0,4)
        int o23  = mt*16 + (lane >> 2) + 8*(ra & 1);
        int qb   = kk*16 + 2*(lane & 3) + 8*(ra >> 1);
        int o2 = o23 >> 3, o3 = o23 & 7;
        float s[2];
        #pragma unroll
        for (int h = 0; h < 2; h++) {
            int q = qb + h;
            int i2 = q >> 3, i3 = q & 7;
            float v = 0.f;
            #pragma unroll
            for (int r3 = 0; r3 < 16; r3++)
                v += w2[(o2*16 + r3)*128 + c*8 + i2] * w3[o3*128 + r3*8 + i3];
            s[h] = v;
        }
        gW23h[c*2048 + rem] = packh2(s[0], s[1]);
    }
}

// ---------------- SMEM map (uint32 indices), 48 KB -> 2 CTAs/SM ----------------
// XH  [0, 4096)      : X B-fragments fp16 (n=q, k=m), per batch 2048 u32:
//   idx = (((b*8 + nt1)*4 + kk)*32 + ((lane + 8*kk)&31))*2 + rb   (bank swizzle)
//   q = nt1*8 + (lane>>2); half2 = m = kk*16 + 2*(lane&3) + 8*rb + {0,1}
// B1H [4096, +2*2048): W01 chunk double-buffer
// B2H [8192, +2*2048): W23 chunk double-buffer
#define B1_OFF 4096
#define B2_OFF 8192
#define SMU_TOTAL 12288

__global__ __launch_bounds__(THREADS, 2)
void tt_mma(const float* __restrict__ x, const float* __restrict__ bias,
            float* __restrict__ out) {
    extern __shared__ uint32_t smu[];
    uint32_t* XH  = smu;
    uint32_t* B1H = smu + B1_OFF;
    uint32_t* B2H = smu + B2_OFF;

    const int tid  = threadIdx.x;
    const int wid  = tid >> 5;
    const int lane = tid & 31;
    const uint32_t sb  = smem_u32(smu);
    const uint32_t B1a = sb + B1_OFF*4u;
    const uint32_t B2a = sb + B2_OFF*4u;

    // prefetch weight chunk 0 (8KB each = 512 uint4)
    {
        const uint4* s01 = (const uint4*)gW01h;
        const uint4* s23 = (const uint4*)gW23h;
        #pragma unroll
        for (int i = 0; i < 2; i++) CPA16(B1a + (tid + i*256)*16, s01 + tid + i*256);
        #pragma unroll
        for (int i = 0; i < 2; i++) CPA16(B2a + (tid + i*256)*16, s23 + tid + i*256);
        CPA_COMMIT();
    }

    // ---- stage X (2 batch rows) into B-fragment layout ----
    // u-fastest thread map: thread handles m-pair u for a q-quad; two row-strided
    // float4 loads give the (m=2u, m=2u+1) value pairs at 4 consecutive q.
    const long long b0 = (long long)blockIdx.x * 2;
    {
        const float4* xp = (const float4*)(x + b0 * 4096);
        #pragma unroll 4
        for (int e = tid; e < 1024; e += THREADS) {
            int u  = e & 31;              // m-pair index: m = 2u, 2u+1
            int qq = (e >> 5) & 15;       // q quad
            int b  = e >> 9;              // batch row (0..1)
            float4 va = xp[b*1024 + (2*u)*16 + qq];
            float4 vb = xp[b*1024 + (2*u + 1)*16 + qq];
            int kk = u >> 3;
            int rb = (u >> 2) & 1;
            int a3 = u & 3;
            float av[4] = {va.x, va.y, va.z, va.w};
            float bv[4] = {vb.x, vb.y, vb.z, vb.w};
            #pragma unroll
            for (int j = 0; j < 4; j++) {
                int q   = qq*4 + j;
                int nt1 = q >> 3;
                int ln  = ((q & 7)*4 + a3 + 8*kk) & 31;   // swizzled physical lane
                XH[(((b*8 + nt1)*4 + kk)*32 + ln)*2 + rb] = packh2(av[j], bv[j]);
            }
        }
    }

    // warp -> (batch bw, oo-quarter ooq): warp owns FULL q, 16 oo cols
    const int bw  = wid >> 2;
    const int ooq = wid & 3;

    float acc[4][2][4];   // [o23-tile][ntl][frag]
    #pragma unroll
    for (int mt = 0; mt < 4; mt++)
        #pragma unroll
        for (int ntl = 0; ntl < 2; ntl++)
            #pragma unroll
            for (int r = 0; r < 4; r++) acc[mt][ntl][r] = 0.f;

    for (int c = 0; c < 16; c++) {
        const int cb = c & 1;
        CPA_WAIT0();
        __syncthreads();   // weights visible; WAR on weight buffers cleared

        if (c < 15) {
            const int nb = cb ^ 1;
            const uint4* s01 = (const uint4*)(gW01h + (c + 1)*2048);
            const uint4* s23 = (const uint4*)(gW23h + (c + 1)*2048);
            #pragma unroll
            for (int i = 0; i < 2; i++) CPA16(B1a + nb*8192 + (tid + i*256)*16, s01 + tid + i*256);
            #pragma unroll
            for (int i = 0; i < 2; i++) CPA16(B2a + nb*8192 + (tid + i*256)*16, s23 + tid + i*256);
            CPA_COMMIT();
        }

        const uint32_t* B1 = B1H + cb*2048;
        const uint32_t* B2 = B2H + cb*2048;

        // ---- stage 1 (swapped): dT[oo(16) x q(64)] = W01_c(A) @ X(B) ----
        // dT C-frag == stage-2 B-frag layout; no shuffles needed.
        float d[8][4];
        #pragma unroll
        for (int nt1 = 0; nt1 < 8; nt1++)
            #pragma unroll
            for (int r = 0; r < 4; r++) d[nt1][r] = 0.f;

        #pragma unroll
        for (int kk = 0; kk < 4; kk++) {
            uint4 af = *(const uint4*)(B1 + ((ooq*4 + kk)*32 + lane)*4);
            uint32_t a[4] = {af.x, af.y, af.z, af.w};
            const uint32_t* xb = XH + ((bw*8)*4 + kk)*32*2 + (((lane + 8*kk) & 31))*2;
            #pragma unroll
            for (int nt1 = 0; nt1 < 8; nt1++) {
                uint2 bf = *(const uint2*)(xb + nt1*(4*32*2));
                mma16816(d[nt1], a, bf.x, bf.y);
            }
        }

        // ---- stage 2: ACC[o23 x oo-slice] += W23_c(A) @ dT(B, direct from C-frags) ----
        #pragma unroll
        for (int K = 0; K < 4; K++) {
            uint32_t bs00 = packh2(d[2*K][0],     d[2*K][1]);      // ntl=0, rb=0
            uint32_t bs01 = packh2(d[2*K + 1][0], d[2*K + 1][1]);  // ntl=0, rb=1
            uint32_t bs10 = packh2(d[2*K][2],     d[2*K][3]);      // ntl=1, rb=0
            uint32_t bs11 = packh2(d[2*K + 1][2], d[2*K + 1][3]);  // ntl=1, rb=1
            #pragma unroll
            for (int mt = 0; mt < 4; mt++) {
                uint4 af = *(const uint4*)(B2 + ((mt*4 + K)*32 + lane)*4);
                uint32_t a[4] = {af.x, af.y, af.z, af.w};
                mma16816(acc[mt][0], a, bs00, bs01);
                mma16816(acc[mt][1], a, bs10, bs11);
            }
        }
    }

    // ---- epilogue: acc element (row=o23, col=oo) + bias -> out ----
    {
        const int g = lane >> 2, tq = lane & 3;
        float* ob = out + (b0 + bw) * 4096;
        #pragma unroll
        for (int mt = 0; mt < 4; mt++)
            #pragma unroll
            for (int ntl = 0; ntl < 2; ntl++)
                #pragma unroll
                for (int r = 0; r < 4; r++) {
                    int o23 = mt*16 + g + 8*(r >> 1);
                    int oo  = ooq*16 + ntl*8 + 2*tq + (r & 1);
                    int col = oo*64 + o23;
                    ob[col] = acc[mt][ntl][r] + __ldg(bias + col);
                }
    }
}

extern "C" void kernel_launch(void* const* d_in, const int* in_sizes, int n_in,
                              void* d_out, int out_size) {
    const float* x    = (const float*)d_in[0];
    const float* w0   = (const float*)d_in[1];
    const float* w1   = (const float*)d_in[2];
    const float* w2   = (const float*)d_in[3];
    const float* w3   = (const float*)d_in[4];
    const float* bias = (const float*)d_in[5];
    float* out = (float*)d_out;

    tt_pre<<<256, 256>>>(w0, w1, w2, w3);

    cudaFuncSetAttribute(tt_mma, cudaFuncAttributeMaxDynamicSharedMemorySize,
                         SMU_TOTAL * (int)sizeof(uint32_t));
    tt_mma<<<16384 / 2, THREADS, SMU_TOTAL * (int)sizeof(uint32_t)>>>(x, bias, out);
}

// round 12
// speedup vs baseline: 2.2239x; 1.0999x over previous
#include <cuda_runtime.h>
#include <cuda_fp16.h>
#include <cstdint>

#define THREADS 256

// ---------------- helpers ----------------
__device__ __forceinline__ uint32_t smem_u32(const void* p){
    uint32_t a;
    asm("{ .reg .u64 t; cvta.to.shared.u64 t, %1; cvt.u32.u64 %0, t; }" : "=r"(a) : "l"(p));
    return a;
}
__device__ __forceinline__ uint32_t packh2(float lo, float hi){
    __half2 h = __floats2half2_rn(lo, hi);
    return *reinterpret_cast<uint32_t*>(&h);
}
__device__ __forceinline__ void mma16816(float d[4], const uint32_t a[4],
                                         const uint32_t b0, const uint32_t b1){
    asm volatile("mma.sync.aligned.m16n8k16.row.col.f32.f16.f16.f32 "
        "{%0,%1,%2,%3}, {%4,%5,%6,%7}, {%8,%9}, {%0,%1,%2,%3};"
        : "+f"(d[0]), "+f"(d[1]), "+f"(d[2]), "+f"(d[3])
        : "r"(a[0]), "r"(a[1]), "r"(a[2]), "r"(a[3]), "r"(b0), "r"(b1));
}
#define CPA16(d, s)  asm volatile("cp.async.cg.shared.global [%0], [%1], 16;" :: "r"(d), "l"(s))
#define CPA_COMMIT() asm volatile("cp.async.commit_group;" ::: "memory")
#define CPA_WAIT0()  asm volatile("cp.async.wait_group 0;" ::: "memory")

// ---------------- merged weights, fp16 fragment-ordered (half2 = uint32) ----------------
// gW01h (stage-1 A operand, M=oo), 16 chunks x 2048 u32, m16n8k16 A-frag order:
//   idx = ((oot*4 + kk)*32 + lane)*4 + ra   (oot = oo tile of 16, [0,4))
//   oo = oot*16 + (lane>>2) + 8*(ra&1); half2 = m = kk*16 + 2*(lane&3) + 8*(ra>>1) + {0,1}
// gW23h (stage-2 A operand, M=o23), same shape:
//   o23 = mt*16 + (lane>>2) + 8*(ra&1); half2 = q = kk*16 + 2*(lane&3) + 8*(ra>>1) + {0,1}
__device__ __align__(16) uint32_t gW01h[32768];
__device__ __align__(16) uint32_t gW23h[32768];

__global__ void tt_pre(const float* __restrict__ w0, const float* __restrict__ w1,
                       const float* __restrict__ w2, const float* __restrict__ w3) {
    int tid = blockIdx.x * blockDim.x + threadIdx.x;
    if (tid < 32768) {
        int c    = tid >> 11;
        int rem  = tid & 2047;
        int ra   = rem & 3;
        int lane = (rem >> 2) & 31;
        int kk   = (rem >> 7) & 3;
        int oot  = rem >> 9;
        int oo   = oot*16 + (lane >> 2) + 8*(ra & 1);
        int mb   = kk*16 + 2*(lane & 3) + 8*(ra >> 1);
        int o0 = oo >> 3, o1 = oo & 7;
        float s[2];
        #pragma unroll
        for (int h = 0; h < 2; h++) {
            int m = mb + h;
            int i0 = m >> 3, i1 = m & 7;
            float v = 0.f;
            #pragma unroll
            for (int r1 = 0; r1 < 16; r1++)
                v += w0[(o0*16 + r1)*8 + i0] * w1[(o1*16 + c)*128 + r1*8 + i1];
            s[h] = v;
        }
        gW01h[c*2048 + rem] = packh2(s[0], s[1]);
    } else if (tid < 65536) {
        int t    = tid - 32768;
        int c    = t >> 11;
        int rem  = t & 2047;
        int ra   = rem & 3;
        int lane = (rem >> 2) & 31;
        int kk   = (rem >> 7) & 3;
        int mt   = rem >> 9;
        int o23  = mt*16 + (lane >> 2) + 8*(ra & 1);
        int qb   = kk*16 + 2*(lane & 3) + 8*(ra >> 1);
        int o2 = o23 >> 3, o3 = o23 & 7;
        float s[2];
        #pragma unroll
        for (int h = 0; h < 2; h++) {
            int q = qb + h;
            int i2 = q >> 3, i3 = q & 7;
            float v = 0.f;
            #pragma unroll
            for (int r3 = 0; r3 < 16; r3++)
                v += w2[(o2*16 + r3)*128 + c*8 + i2] * w3[o3*128 + r3*8 + i3];
            s[h] = v;
        }
        gW23h[c*2048 + rem] = packh2(s[0], s[1]);
    }
}

// ---------------- SMEM map (uint32 indices), 64 KB, 1 CTA/SM ----------------
// XH  [0, 8192)       : X B-fragments fp16 (n=q, k=m), 4 batches x 2048 u32:
//   idx = (((b*8 + nt1)*4 + kk)*32 + ((lane + 8*kk)&31))*2 + rb   (bank swizzle)
//   q = nt1*8 + (lane>>2); half2 = m = kk*16 + 2*(lane&3) + 8*rb + {0,1}
// B1H [8192,  +2*2048): W01 chunk double-buffer
// B2H [12288, +2*2048): W23 chunk double-buffer
#define B1_OFF 8192
#define B2_OFF 12288
#define SMU_TOTAL 16384

__global__ __launch_bounds__(THREADS, 1)
void tt_mma(const float* __restrict__ x, const float* __restrict__ bias,
            float* __restrict__ out) {
    extern __shared__ uint32_t smu[];
    uint32_t* XH  = smu;
    uint32_t* B1H = smu + B1_OFF;
    uint32_t* B2H = smu + B2_OFF;

    const int tid  = threadIdx.x;
    const int wid  = tid >> 5;
    const int lane = tid & 31;
    const uint32_t sb  = smem_u32(smu);
    const uint32_t B1a = sb + B1_OFF*4u;
    const uint32_t B2a = sb + B2_OFF*4u;

    // prefetch weight chunk 0 (8KB each = 512 uint4)
    {
        const uint4* s01 = (const uint4*)gW01h;
        const uint4* s23 = (const uint4*)gW23h;
        #pragma unroll
        for (int i = 0; i < 2; i++) CPA16(B1a + (tid + i*256)*16, s01 + tid + i*256);
        #pragma unroll
        for (int i = 0; i < 2; i++) CPA16(B2a + (tid + i*256)*16, s23 + tid + i*256);
        CPA_COMMIT();
    }

    // ---- stage X (4 batch rows) into B-fragment layout in smem ----
    const long long b0 = (long long)blockIdx.x * 4;
    {
        const float4* xp = (const float4*)(x + b0 * 4096);
        #pragma unroll 4
        for (int e = tid; e < 2048; e += THREADS) {
            int u  = e & 31;              // m-pair index: m = 2u, 2u+1
            int qq = (e >> 5) & 15;       // q quad
            int b  = e >> 9;              // batch row (0..3)
            float4 va = xp[b*1024 + (2*u)*16 + qq];
            float4 vb = xp[b*1024 + (2*u + 1)*16 + qq];
            int kk = u >> 3;
            int rb = (u >> 2) & 1;
            int a3 = u & 3;
            float av[4] = {va.x, va.y, va.z, va.w};
            float bv[4] = {vb.x, vb.y, vb.z, vb.w};
            #pragma unroll
            for (int j = 0; j < 4; j++) {
                int q   = qq*4 + j;
                int nt1 = q >> 3;
                int ln  = ((q & 7)*4 + a3 + 8*kk) & 31;   // swizzled physical lane
                XH[(((b*8 + nt1)*4 + kk)*32 + ln)*2 + rb] = packh2(av[j], bv[j]);
            }
        }
    }
    __syncthreads();

    // warp -> (batch bw, oo-half ooh): warp owns FULL q, 32 oo cols
    const int bw  = wid >> 1;
    const int ooh = wid & 1;

    // ---- load this warp's X B-fragments into registers (chunk-invariant) ----
    uint32_t xr[4][8][2];   // [kk][nt1][rb] = 64 regs
    #pragma unroll
    for (int kk = 0; kk < 4; kk++) {
        const int ln = (lane + 8*kk) & 31;
        #pragma unroll
        for (int nt1 = 0; nt1 < 8; nt1++) {
            uint2 bf = *(const uint2*)(XH + (((bw*8 + nt1)*4 + kk)*32 + ln)*2);
            xr[kk][nt1][0] = bf.x;
            xr[kk][nt1][1] = bf.y;
        }
    }

    float acc[4][4][4];   // [o23-tile mt][ntl = mt1*2+ntl_in][frag]
    #pragma unroll
    for (int mt = 0; mt < 4; mt++)
        #pragma unroll
        for (int ntl = 0; ntl < 4; ntl++)
            #pragma unroll
            for (int r = 0; r < 4; r++) acc[mt][ntl][r] = 0.f;

    for (int c = 0; c < 16; c++) {
        const int cb = c & 1;
        CPA_WAIT0();
        __syncthreads();   // weights visible; WAR on weight buffers cleared

        if (c < 15) {
            const int nb = cb ^ 1;
            const uint4* s01 = (const uint4*)(gW01h + (c + 1)*2048);
            const uint4* s23 = (const uint4*)(gW23h + (c + 1)*2048);
            #pragma unroll
            for (int i = 0; i < 2; i++) CPA16(B1a + nb*8192 + (tid + i*256)*16, s01 + tid + i*256);
            #pragma unroll
            for (int i = 0; i < 2; i++) CPA16(B2a + nb*8192 + (tid + i*256)*16, s23 + tid + i*256);
            CPA_COMMIT();
        }

        const uint32_t* B1 = B1H + cb*2048;
        const uint32_t* B2 = B2H + cb*2048;

        // ---- stage 1: dT[oo(32) x q(64)] = W01_c(A) @ X(B, registers) ----
        float d[2][8][4];
        #pragma unroll
        for (int mt1 = 0; mt1 < 2; mt1++)
            #pragma unroll
            for (int nt1 = 0; nt1 < 8; nt1++)
                #pragma unroll
                for (int r = 0; r < 4; r++) d[mt1][nt1][r] = 0.f;

        #pragma unroll
        for (int kk = 0; kk < 4; kk++) {
            #pragma unroll
            for (int mt1 = 0; mt1 < 2; mt1++) {
                const int oot = ooh*2 + mt1;
                uint4 af = *(const uint4*)(B1 + ((oot*4 + kk)*32 + lane)*4);
                uint32_t a[4] = {af.x, af.y, af.z, af.w};
                #pragma unroll
                for (int nt1 = 0; nt1 < 8; nt1++)
                    mma16816(d[mt1][nt1], a, xr[kk][nt1][0], xr[kk][nt1][1]);
            }
        }

        // ---- stage 2: ACC[o23(64) x oo(32)] += W23_c(A) @ dT(B from C-frags) ----
        #pragma unroll
        for (int K = 0; K < 4; K++) {
            uint32_t bs[4][2];   // [ntl = mt1*2+ntl_in][rb]
            #pragma unroll
            for (int mt1 = 0; mt1 < 2; mt1++) {
                bs[mt1*2 + 0][0] = packh2(d[mt1][2*K][0],     d[mt1][2*K][1]);
                bs[mt1*2 + 0][1] = packh2(d[mt1][2*K + 1][0], d[mt1][2*K + 1][1]);
                bs[mt1*2 + 1][0] = packh2(d[mt1][2*K][2],     d[mt1][2*K][3]);
                bs[mt1*2 + 1][1] = packh2(d[mt1][2*K + 1][2], d[mt1][2*K + 1][3]);
            }
            #pragma unroll
            for (int mt = 0; mt < 4; mt++) {
                uint4 af = *(const uint4*)(B2 + ((mt*4 + K)*32 + lane)*4);
                uint32_t a[4] = {af.x, af.y, af.z, af.w};
                #pragma unroll
                for (int ntl = 0; ntl < 4; ntl++)
                    mma16816(acc[mt][ntl], a, bs[ntl][0], bs[ntl][1]);
            }
        }
    }

    // ---- epilogue: acc element (row=o23, col=oo) + bias -> out ----
    {
        const int g = lane >> 2, tq = lane & 3;
        float* ob = out + (b0 + bw) * 4096;
        #pragma unroll
        for (int mt = 0; mt < 4; mt++)
            #pragma unroll
            for (int ntl = 0; ntl < 4; ntl++)
                #pragma unroll
                for (int r = 0; r < 4; r++) {
                    int o23 = mt*16 + g + 8*(r >> 1);
                    int oo  = ooh*32 + ntl*8 + 2*tq + (r & 1);
                    int col = oo*64 + o23;
                    ob[col] = acc[mt][ntl][r] + __ldg(bias + col);
                }
    }
}

extern "C" void kernel_launch(void* const* d_in, const int* in_sizes, int n_in,
                              void* d_out, int out_size) {
    const float* x    = (const float*)d_in[0];
    const float* w0   = (const float*)d_in[1];
    const float* w1   = (const float*)d_in[2];
    const float* w2   = (const float*)d_in[3];
    const float* w3   = (const float*)d_in[4];
    const float* bias = (const float*)d_in[5];
    float* out = (float*)d_out;

    tt_pre<<<256, 256>>>(w0, w1, w2, w3);

    cudaFuncSetAttribute(tt_mma, cudaFuncAttributeMaxDynamicSharedMemorySize,
                         SMU_TOTAL * (int)sizeof(uint32_t));
    tt_mma<<<16384 / 4, THREADS, SMU_TOTAL * (int)sizeof(uint32_t)>>>(x, bias, out);
}